// round 12
// baseline (speedup 1.0000x reference)
#include <cuda_runtime.h>
#include <cuda_bf16.h>
#include <cstdint>

#define NN   50000
#define NE   800000
#define TE   850000   // NE + NN self loops
#define FDIM 256
#define NH   4
#define HD   64
#define NG   128
#define OD   10

// ---------------- scratch (device globals) ---------------------------------
__device__ __nv_bfloat16 g_h[NN * FDIM];     // h = in @ W (bf16 messages)
__device__ __nv_bfloat16 g_feat[NN * FDIM];  // layer output features (bf16)
__device__ float g_asrc[NN * NH];
__device__ float g_adst[NN * NH];
// CSR (built once per launch; same edges both layers)
__device__ int   g_deg[NN];
__device__ int   g_off[NN + 1];
__device__ int   g_cur[NN];
__device__ int   g_csrc[TE];

// ---------------- CSR build ------------------------------------------------
__global__ void k_count(const int* __restrict__ ei) {
    int idx = blockIdx.x * blockDim.x + threadIdx.x;
    if (idx >= TE) return;
    int d = (idx < NE) ? ei[NE + idx] : (idx - NE);
    atomicAdd(&g_deg[d], 1);
}

__global__ __launch_bounds__(1024) void k_scan() {
    const int t = threadIdx.x;
    const int CH = (NN + 1023) / 1024;   // 49
    __shared__ int sh[1024];
    int base = t * CH;
    int sum = 0;
    for (int i = 0; i < CH; i++) {
        int idx = base + i;
        if (idx < NN) sum += g_deg[idx];
    }
    sh[t] = sum;
    __syncthreads();
    for (int off = 1; off < 1024; off <<= 1) {
        int v = (t >= off) ? sh[t - off] : 0;
        __syncthreads();
        sh[t] += v;
        __syncthreads();
    }
    int run = (t == 0) ? 0 : sh[t - 1];
    for (int i = 0; i < CH; i++) {
        int idx = base + i;
        if (idx < NN) {
            g_off[idx] = run;
            g_cur[idx] = 0;
            run += g_deg[idx];
        }
    }
    if (t == 1023) g_off[NN] = sh[1023];
}

__global__ void k_scatter(const int* __restrict__ ei) {
    int idx = blockIdx.x * blockDim.x + threadIdx.x;
    if (idx >= TE) return;
    int s, d;
    if (idx < NE) { s = ei[idx]; d = ei[NE + idx]; }
    else          { s = d = idx - NE; }
    int p = g_off[d] + atomicAdd(&g_cur[d], 1);
    g_csrc[p] = s;
}

// ---------------- helpers ---------------------------------------------------
__device__ __forceinline__ uint32_t s2u(const void* p) {
    return (uint32_t)__cvta_generic_to_shared(p);
}
__device__ __forceinline__ void cpa16(uint32_t dst, const void* src) {
    asm volatile("cp.async.cg.shared.global [%0], [%1], 16;"
                 :: "r"(dst), "l"(src));
}
__device__ __forceinline__ void cpa16p(uint32_t dst, const void* src, int sz) {
    asm volatile("cp.async.cg.shared.global [%0], [%1], 16, %2;"
                 :: "r"(dst), "l"(src), "r"(sz));
}
__device__ __forceinline__ float to_tf32(float x) {
    float r;
    asm("cvt.rna.tf32.f32 %0, %1;" : "=f"(r) : "f"(x));
    return r;
}

// ---------------- tf32 GEMM + fused attention epilogue ----------------------
// W stays fp32->tf32: shared quantization of W propagates coherently through
// pooling (bf16 W would cost ~1.5e-3) - never quantize it.
#define BS_LD 136
#define B_BYTES (2 * 32 * BS_LD * 4)
#define EXTRA_BYTES ((256 + 1024) * 4)

template <typename AT>
__global__ __launch_bounds__(256, 2) void k_gemm_attn(const AT* __restrict__ A,
                                                      const float* __restrict__ B,
                                                      __nv_bfloat16* __restrict__ C,
                                                      const float* __restrict__ att_s,
                                                      const float* __restrict__ att_d,
                                                      int M) {
    constexpr bool A32 = (sizeof(AT) == 4);
    constexpr int AS_LDW = A32 ? 36 : 40;
    constexpr int A_BYTES = 2 * 128 * AS_LDW * (int)sizeof(AT);

    extern __shared__ char smc[];
    AT (*As)[128][AS_LDW] = reinterpret_cast<AT (*)[128][AS_LDW]>(smc);
    float (*Bs)[32][BS_LD] = reinterpret_cast<float (*)[32][BS_LD]>(smc + A_BYTES);
    float* satt = reinterpret_cast<float*>(smc + A_BYTES + B_BYTES);
    float* datt = satt + 128;
    float (*sps)[4] = reinterpret_cast<float (*)[4]>(datt + 128);
    float (*spd)[4] = reinterpret_cast<float (*)[4]>(datt + 128 + 512);

    const int tid = threadIdx.x;
    const int wid = tid >> 5, lane = tid & 31;
    const int warp_m = wid >> 2;
    const int warp_n = wid & 3;
    const int bm = blockIdx.x * 128;
    const int by = blockIdx.y;
    const int bn = by * 128;
    const int r = lane >> 2, c = lane & 3;

    if (tid < 128) {
        satt[tid] = att_s[by * 128 + tid];
        datt[tid] = att_d[by * 128 + tid];
    }

    float acc[4][4][4];
#pragma unroll
    for (int i = 0; i < 4; i++)
#pragma unroll
        for (int j = 0; j < 4; j++)
#pragma unroll
            for (int q = 0; q < 4; q++) acc[i][j][q] = 0.f;

    auto stage_load = [&](int st, int k0) {
        if constexpr (A32) {
#pragma unroll
            for (int i = 0; i < 4; i++) {
                int idx = tid + i * 256;
                int row = idx >> 3;
                int k4  = (idx & 7) << 2;
                cpa16p(s2u(&As[st][row][k4]), &A[(bm + row) * 256 + k0 + k4],
                       (bm + row < M) ? 16 : 0);
            }
        } else {
#pragma unroll
            for (int i = 0; i < 2; i++) {
                int idx = tid + i * 256;
                int row = idx >> 2;
                int k8  = (idx & 3) << 3;
                cpa16p(s2u(&As[st][row][k8]), &A[(bm + row) * 256 + k0 + k8],
                       (bm + row < M) ? 16 : 0);
            }
        }
#pragma unroll
        for (int i = 0; i < 4; i++) {
            int idx = tid + i * 256;
            int kk = idx >> 5;
            int n4 = (idx & 31) << 2;
            cpa16(s2u(&Bs[st][kk][n4]), &B[(k0 + kk) * 256 + bn + n4]);
        }
        asm volatile("cp.async.commit_group;");
    };

    auto afrag = [&](int cur, int m, int k) -> float {
        if constexpr (A32) return to_tf32(As[cur][m][k]);
        else               return __bfloat162float(As[cur][m][k]);
    };

    stage_load(0, 0);
    for (int t = 0; t < 8; t++) {
        const int cur = t & 1;
        if (t < 7) {
            stage_load(cur ^ 1, (t + 1) * 32);
            asm volatile("cp.async.wait_group 1;");
        } else {
            asm volatile("cp.async.wait_group 0;");
        }
        __syncthreads();
#pragma unroll
        for (int ks = 0; ks < 4; ks++) {
            const int kb = ks * 8;
            float a[4][4], b[4][2];
#pragma unroll
            for (int mt = 0; mt < 4; mt++) {
                int m0 = warp_m * 64 + mt * 16;
                a[mt][0] = afrag(cur, m0 + r, kb + c);
                a[mt][1] = afrag(cur, m0 + 8 + r, kb + c);
                a[mt][2] = afrag(cur, m0 + r, kb + 4 + c);
                a[mt][3] = afrag(cur, m0 + 8 + r, kb + 4 + c);
            }
#pragma unroll
            for (int nt = 0; nt < 4; nt++) {
                int n0 = warp_n * 32 + nt * 8;
                b[nt][0] = to_tf32(Bs[cur][kb + c][n0 + r]);
                b[nt][1] = to_tf32(Bs[cur][kb + 4 + c][n0 + r]);
            }
#pragma unroll
            for (int mt = 0; mt < 4; mt++)
#pragma unroll
                for (int nt = 0; nt < 4; nt++) {
                    asm volatile(
                        "mma.sync.aligned.m16n8k8.row.col.f32.tf32.tf32.f32 "
                        "{%0,%1,%2,%3}, {%4,%5,%6,%7}, {%8,%9}, {%0,%1,%2,%3};"
                        : "+f"(acc[mt][nt][0]), "+f"(acc[mt][nt][1]),
                          "+f"(acc[mt][nt][2]), "+f"(acc[mt][nt][3])
                        : "f"(a[mt][0]), "f"(a[mt][1]), "f"(a[mt][2]), "f"(a[mt][3]),
                          "f"(b[nt][0]), "f"(b[nt][1]));
                }
        }
        __syncthreads();
    }

    // ---- store C as bf16 ----
#pragma unroll
    for (int mt = 0; mt < 4; mt++) {
        int row0 = bm + warp_m * 64 + mt * 16 + r;
#pragma unroll
        for (int nt = 0; nt < 4; nt++) {
            int col = bn + warp_n * 32 + nt * 8 + c * 2;
            if (row0 < M)
                *(__nv_bfloat162*)&C[row0 * 256 + col] =
                    __floats2bfloat162_rn(acc[mt][nt][0], acc[mt][nt][1]);
            if (row0 + 8 < M)
                *(__nv_bfloat162*)&C[(row0 + 8) * 256 + col] =
                    __floats2bfloat162_rn(acc[mt][nt][2], acc[mt][nt][3]);
        }
    }

    // ---- fused attention epilogue (fp32 accs) ----
    float ps[8], pd[8];
#pragma unroll
    for (int mt = 0; mt < 4; mt++) {
        float s_lo = 0.f, s_hi = 0.f, d_lo = 0.f, d_hi = 0.f;
#pragma unroll
        for (int nt = 0; nt < 4; nt++) {
            int cl = warp_n * 32 + nt * 8 + c * 2;
            float w0s = satt[cl], w1s = satt[cl + 1];
            float w0d = datt[cl], w1d = datt[cl + 1];
            s_lo += acc[mt][nt][0] * w0s + acc[mt][nt][1] * w1s;
            s_hi += acc[mt][nt][2] * w0s + acc[mt][nt][3] * w1s;
            d_lo += acc[mt][nt][0] * w0d + acc[mt][nt][1] * w1d;
            d_hi += acc[mt][nt][2] * w0d + acc[mt][nt][3] * w1d;
        }
        ps[mt * 2] = s_lo; ps[mt * 2 + 1] = s_hi;
        pd[mt * 2] = d_lo; pd[mt * 2 + 1] = d_hi;
    }
#pragma unroll
    for (int i = 0; i < 8; i++) {
        ps[i] += __shfl_xor_sync(0xffffffffu, ps[i], 1);
        ps[i] += __shfl_xor_sync(0xffffffffu, ps[i], 2);
        pd[i] += __shfl_xor_sync(0xffffffffu, pd[i], 1);
        pd[i] += __shfl_xor_sync(0xffffffffu, pd[i], 2);
    }
    if (c == 0) {
#pragma unroll
        for (int mt = 0; mt < 4; mt++) {
            int rl = warp_m * 64 + mt * 16 + r;
            sps[rl][warp_n]     = ps[mt * 2];
            spd[rl][warp_n]     = pd[mt * 2];
            sps[rl + 8][warp_n] = ps[mt * 2 + 1];
            spd[rl + 8][warp_n] = pd[mt * 2 + 1];
        }
    }
    __syncthreads();
    {
        int row = tid & 127;
        int hh  = tid >> 7;
        if (bm + row < M) {
            float vs = sps[row][hh * 2] + sps[row][hh * 2 + 1];
            float vd = spd[row][hh * 2] + spd[row][hh * 2 + 1];
            g_asrc[(bm + row) * 4 + by * 2 + hh] = vs;
            g_adst[(bm + row) * 4 + by * 2 + hh] = vd;
        }
    }
}

#define GEMM_SMEM_F32  (2 * 128 * 36 * 4 + B_BYTES + EXTRA_BYTES)
#define GEMM_SMEM_BF16 (2 * 128 * 40 * 2 + B_BYTES + EXTRA_BYTES)

// ---------------- aggregate: cp.async-pipelined gather ----------------------
__device__ __forceinline__ void bf8_fma(const uint4& q, float ex,
                                        float& a0, float& a1, float& a2, float& a3,
                                        float& a4, float& a5, float& a6, float& a7) {
    float2 f0 = __bfloat1622float2(*(const __nv_bfloat162*)&q.x);
    float2 f1 = __bfloat1622float2(*(const __nv_bfloat162*)&q.y);
    float2 f2 = __bfloat1622float2(*(const __nv_bfloat162*)&q.z);
    float2 f3 = __bfloat1622float2(*(const __nv_bfloat162*)&q.w);
    a0 = fmaf(f0.x, ex, a0); a1 = fmaf(f0.y, ex, a1);
    a2 = fmaf(f1.x, ex, a2); a3 = fmaf(f1.y, ex, a3);
    a4 = fmaf(f2.x, ex, a4); a5 = fmaf(f2.y, ex, a5);
    a6 = fmaf(f3.x, ex, a6); a7 = fmaf(f3.y, ex, a7);
}

// one warp per dst node; h-rows staged via cp.async double buffer (per warp).
__global__ __launch_bounds__(256) void k_agg(const __nv_bfloat16* __restrict__ h,
                                             const float* __restrict__ bias,
                                             __nv_bfloat16* __restrict__ feat) {
    __shared__ __align__(16) __nv_bfloat16 sbuf[8][2][4][256];   // 32 KB
    const int wid  = threadIdx.x >> 5;
    const int lane = threadIdx.x & 31;
    const int node = blockIdx.x * 8 + wid;
    if (node >= NN) return;
    const int beg = g_off[node], end = g_off[node + 1];
    const int h4 = lane >> 3;
    const float adh = g_adst[node * 4 + h4];

    float dn = 0.f;
    float a0 = 0.f, a1 = 0.f, a2 = 0.f, a3 = 0.f;
    float a4 = 0.f, a5 = 0.f, a6 = 0.f, a7 = 0.f;

    const int nb = (end - beg) >> 2;    // full batches of 4 edges
    int j = beg;

    int   sA0, sA1, sA2, sA3, sB0, sB1, sB2, sB3;
    float eA0, eA1, eA2, eA3, eB0, eB1, eB2, eB3;

#define AGG_GATHER(S0,S1,S2,S3,E0,E1,E2,E3,JJ)                                 \
    do {                                                                       \
        S0 = g_csrc[(JJ) + 0]; S1 = g_csrc[(JJ) + 1];                          \
        S2 = g_csrc[(JJ) + 2]; S3 = g_csrc[(JJ) + 3];                          \
        E0 = g_asrc[S0 * 4 + h4]; E1 = g_asrc[S1 * 4 + h4];                    \
        E2 = g_asrc[S2 * 4 + h4]; E3 = g_asrc[S3 * 4 + h4];                    \
    } while (0)

#define AGG_ISSUE(ST,S0,S1,S2,S3)                                              \
    do {                                                                       \
        cpa16(s2u(&sbuf[wid][ST][0][lane * 8]), &h[(size_t)S0 * 256 + lane * 8]); \
        cpa16(s2u(&sbuf[wid][ST][1][lane * 8]), &h[(size_t)S1 * 256 + lane * 8]); \
        cpa16(s2u(&sbuf[wid][ST][2][lane * 8]), &h[(size_t)S2 * 256 + lane * 8]); \
        cpa16(s2u(&sbuf[wid][ST][3][lane * 8]), &h[(size_t)S3 * 256 + lane * 8]); \
        asm volatile("cp.async.commit_group;");                                \
    } while (0)

#define AGG_COMPUTE(ST,E0,E1,E2,E3)                                            \
    do {                                                                       \
        float e0 = E0 + adh, e1 = E1 + adh, e2 = E2 + adh, e3 = E3 + adh;      \
        e0 = e0 > 0.f ? e0 : 0.2f * e0;  e1 = e1 > 0.f ? e1 : 0.2f * e1;       \
        e2 = e2 > 0.f ? e2 : 0.2f * e2;  e3 = e3 > 0.f ? e3 : 0.2f * e3;       \
        float x0 = __expf(e0), x1 = __expf(e1);                                \
        float x2 = __expf(e2), x3 = __expf(e3);                                \
        dn += (x0 + x1) + (x2 + x3);                                           \
        uint4 q0 = *(const uint4*)&sbuf[wid][ST][0][lane * 8];                 \
        uint4 q1 = *(const uint4*)&sbuf[wid][ST][1][lane * 8];                 \
        uint4 q2 = *(const uint4*)&sbuf[wid][ST][2][lane * 8];                 \
        uint4 q3 = *(const uint4*)&sbuf[wid][ST][3][lane * 8];                 \
        bf8_fma(q0, x0, a0, a1, a2, a3, a4, a5, a6, a7);                       \
        bf8_fma(q1, x1, a0, a1, a2, a3, a4, a5, a6, a7);                       \
        bf8_fma(q2, x2, a0, a1, a2, a3, a4, a5, a6, a7);                       \
        bf8_fma(q3, x3, a0, a1, a2, a3, a4, a5, a6, a7);                       \
    } while (0)

    if (nb > 0) {
        AGG_GATHER(sA0, sA1, sA2, sA3, eA0, eA1, eA2, eA3, j);
        AGG_ISSUE(0, sA0, sA1, sA2, sA3);
        int i = 0;
        while (true) {
            // even batch: compute stage 0 (A), prefetch into stage 1 (B)
            if (i + 1 < nb) {
                AGG_GATHER(sB0, sB1, sB2, sB3, eB0, eB1, eB2, eB3, j + 4);
                AGG_ISSUE(1, sB0, sB1, sB2, sB3);
                asm volatile("cp.async.wait_group 1;");
            } else {
                asm volatile("cp.async.wait_group 0;");
            }
            AGG_COMPUTE(0, eA0, eA1, eA2, eA3);
            j += 4; i++;
            if (i >= nb) break;
            // odd batch: compute stage 1 (B), prefetch into stage 0 (A)
            if (i + 1 < nb) {
                AGG_GATHER(sA0, sA1, sA2, sA3, eA0, eA1, eA2, eA3, j + 4);
                AGG_ISSUE(0, sA0, sA1, sA2, sA3);
                asm volatile("cp.async.wait_group 1;");
            } else {
                asm volatile("cp.async.wait_group 0;");
            }
            AGG_COMPUTE(1, eB0, eB1, eB2, eB3);
            j += 4; i++;
            if (i >= nb) break;
        }
    }
    // tail (<4 edges): direct global loads
    for (; j < end; j++) {
        int s = g_csrc[j];
        float e = g_asrc[s * 4 + h4] + adh;
        e = e > 0.f ? e : 0.2f * e;
        float ex = __expf(e);
        uint4 q = *(const uint4*)&h[(size_t)s * 256 + lane * 8];
        dn += ex;
        bf8_fma(q, ex, a0, a1, a2, a3, a4, a5, a6, a7);
    }

    const float inv = 1.f / (dn + 1e-16f);
    float4 b0 = *(const float4*)&bias[lane * 8];
    float4 b1 = *(const float4*)&bias[lane * 8 + 4];
    float o[8];
    o[0] = fmaf(a0, inv, b0.x); o[1] = fmaf(a1, inv, b0.y);
    o[2] = fmaf(a2, inv, b0.z); o[3] = fmaf(a3, inv, b0.w);
    o[4] = fmaf(a4, inv, b1.x); o[5] = fmaf(a5, inv, b1.y);
    o[6] = fmaf(a6, inv, b1.z); o[7] = fmaf(a7, inv, b1.w);
#pragma unroll
    for (int i = 0; i < 8; i++) o[i] = o[i] > 0.f ? o[i] : 0.f;
    uint4 qo;
    *(__nv_bfloat162*)&qo.x = __floats2bfloat162_rn(o[0], o[1]);
    *(__nv_bfloat162*)&qo.y = __floats2bfloat162_rn(o[2], o[3]);
    *(__nv_bfloat162*)&qo.z = __floats2bfloat162_rn(o[4], o[5]);
    *(__nv_bfloat162*)&qo.w = __floats2bfloat162_rn(o[6], o[7]);
    *(uint4*)&feat[node * 256 + lane * 8] = qo;
}

// ---------------- fused pool (sorted batch) + head --------------------------
__global__ __launch_bounds__(256) void k_poolhead(const int* __restrict__ batch,
                                                  const float* __restrict__ Wf,
                                                  const float* __restrict__ bf,
                                                  float* __restrict__ out,
                                                  int out_size) {
    const int g = blockIdx.x;
    const int t = threadIdx.x;
    __shared__ int s_bnd[2];
    __shared__ float sp[256];
    if (t < 2) {
        int key = g + t;
        int lo = 0, hi = NN;
        while (lo < hi) {
            int mid = (lo + hi) >> 1;
            if (batch[mid] < key) lo = mid + 1; else hi = mid;
        }
        s_bnd[t] = lo;
    }
    __syncthreads();
    const int lo = s_bnd[0], hi = s_bnd[1];
    float s0 = 0.f, s1 = 0.f, s2 = 0.f, s3 = 0.f;
    float s4 = 0.f, s5 = 0.f, s6 = 0.f, s7 = 0.f;
    int n = lo;
    for (; n + 7 < hi; n += 8) {
        s0 += __bfloat162float(g_feat[(n + 0) * 256 + t]);
        s1 += __bfloat162float(g_feat[(n + 1) * 256 + t]);
        s2 += __bfloat162float(g_feat[(n + 2) * 256 + t]);
        s3 += __bfloat162float(g_feat[(n + 3) * 256 + t]);
        s4 += __bfloat162float(g_feat[(n + 4) * 256 + t]);
        s5 += __bfloat162float(g_feat[(n + 5) * 256 + t]);
        s6 += __bfloat162float(g_feat[(n + 6) * 256 + t]);
        s7 += __bfloat162float(g_feat[(n + 7) * 256 + t]);
    }
    for (; n < hi; n++) s0 += __bfloat162float(g_feat[n * 256 + t]);
    float cnt = (float)(hi - lo);
    cnt = cnt < 1.f ? 1.f : cnt;
    float p = (((s0 + s1) + (s2 + s3)) + ((s4 + s5) + (s6 + s7))) / cnt;
    if (out_size >= NG * OD + NG * FDIM)
        out[NG * OD + g * 256 + t] = p;
    sp[t] = p;
    __syncthreads();
    if (t < OD) {
        float s = 0.f;
        for (int c = 0; c < 256; c++) s += sp[c] * Wf[c * OD + t];
        out[g * OD + t] = s + bf[t];
    }
}

// ---------------- launch ---------------------------------------------------
extern "C" void kernel_launch(void* const* d_in, const int* in_sizes, int n_in,
                              void* d_out, int out_size) {
    const float* x     = (const float*)d_in[0];
    const int*   ei    = (const int*)d_in[1];
    const int*   batch = (const int*)d_in[3];
    const float* W1  = (const float*)d_in[4];
    const float* as1 = (const float*)d_in[5];
    const float* ad1 = (const float*)d_in[6];
    const float* b1  = (const float*)d_in[7];
    const float* W2  = (const float*)d_in[8];
    const float* as2 = (const float*)d_in[9];
    const float* ad2 = (const float*)d_in[10];
    const float* b2  = (const float*)d_in[11];
    const float* Wf  = (const float*)d_in[12];
    const float* bf  = (const float*)d_in[13];
    float* out = (float*)d_out;

    __nv_bfloat16 *p_h, *p_feat;
    int* p_deg;
    cudaGetSymbolAddress((void**)&p_h, g_h);
    cudaGetSymbolAddress((void**)&p_feat, g_feat);
    cudaGetSymbolAddress((void**)&p_deg, g_deg);

    // lazily created once (first call = correctness run, outside graph capture)
    static cudaStream_t s_side = nullptr;
    static cudaEvent_t  ev_fork = nullptr, ev_join = nullptr;
    static bool s_attr_done = false;
    if (!s_side) {
        cudaStreamCreateWithFlags(&s_side, cudaStreamNonBlocking);
        cudaEventCreateWithFlags(&ev_fork, cudaEventDisableTiming);
        cudaEventCreateWithFlags(&ev_join, cudaEventDisableTiming);
    }
    if (!s_attr_done) {
        cudaFuncSetAttribute(k_gemm_attn<float>,
                             cudaFuncAttributeMaxDynamicSharedMemorySize,
                             GEMM_SMEM_F32);
        cudaFuncSetAttribute(k_gemm_attn<__nv_bfloat16>,
                             cudaFuncAttributeMaxDynamicSharedMemorySize,
                             GEMM_SMEM_BF16);
        s_attr_done = true;
    }

    const int GEMM_MB = (NN + 127) / 128;
    const int TE_BLK  = (TE + 255) / 256;
    const int AGG_BLK = (NN + 7) / 8;    // 8 warps/block

    // ---- fork: CSR build on side stream, overlapped with layer-1 GEMM ----
    cudaEventRecord(ev_fork, 0);
    cudaStreamWaitEvent(s_side, ev_fork, 0);
    cudaMemsetAsync(p_deg, 0, NN * sizeof(int), s_side);
    k_count<<<TE_BLK, 256, 0, s_side>>>(ei);
    k_scan<<<1, 1024, 0, s_side>>>();
    k_scatter<<<TE_BLK, 256, 0, s_side>>>(ei);
    cudaEventRecord(ev_join, s_side);

    // ---- layer 1 GEMM (origin stream, concurrent with CSR build) ----
    k_gemm_attn<float><<<dim3(GEMM_MB, 2), 256, GEMM_SMEM_F32>>>(
        x, W1, p_h, as1, ad1, NN);

    // ---- join: agg needs both CSR and GEMM-1 results ----
    cudaStreamWaitEvent(0, ev_join, 0);
    k_agg<<<AGG_BLK, 256>>>(p_h, b1, p_feat);

    // ---- layer 2 ----
    k_gemm_attn<__nv_bfloat16><<<dim3(GEMM_MB, 2), 256, GEMM_SMEM_BF16>>>(
        p_feat, W2, p_h, as2, ad2, NN);
    k_agg<<<AGG_BLK, 256>>>(p_h, b2, p_feat);

    // ---- fused pool + head ----
    k_poolhead<<<NG, 256>>>(batch, Wf, bf, out, out_size);
}

// round 13
// speedup vs baseline: 1.0119x; 1.0119x over previous
#include <cuda_runtime.h>
#include <cuda_bf16.h>
#include <cuda_fp8.h>
#include <cstdint>

#define NN   50000
#define NE   800000
#define TE   850000   // NE + NN self loops
#define FDIM 256
#define NH   4
#define HD   64
#define NG   128
#define OD   10

// ---------------- scratch (device globals) ---------------------------------
// g_h: layer-1 messages stored as fp8 e4m3 (first 12.8MB), layer-2 as bf16.
__device__ __align__(16) unsigned char g_h[NN * FDIM * 2];
__device__ __nv_bfloat16 g_feat[NN * FDIM];  // layer output features (bf16)
__device__ float g_asrc[NN * NH];
__device__ float g_adst[NN * NH];
// CSR (built once per launch; same edges both layers)
__device__ int   g_deg[NN];
__device__ int   g_off[NN + 1];
__device__ int   g_cur[NN];
__device__ int   g_csrc[TE];

// ---------------- CSR build ------------------------------------------------
__global__ void k_count(const int* __restrict__ ei) {
    int idx = blockIdx.x * blockDim.x + threadIdx.x;
    if (idx >= TE) return;
    int d = (idx < NE) ? ei[NE + idx] : (idx - NE);
    atomicAdd(&g_deg[d], 1);
}

__global__ __launch_bounds__(1024) void k_scan() {
    const int t = threadIdx.x;
    const int CH = (NN + 1023) / 1024;   // 49
    __shared__ int sh[1024];
    int base = t * CH;
    int sum = 0;
    for (int i = 0; i < CH; i++) {
        int idx = base + i;
        if (idx < NN) sum += g_deg[idx];
    }
    sh[t] = sum;
    __syncthreads();
    for (int off = 1; off < 1024; off <<= 1) {
        int v = (t >= off) ? sh[t - off] : 0;
        __syncthreads();
        sh[t] += v;
        __syncthreads();
    }
    int run = (t == 0) ? 0 : sh[t - 1];
    for (int i = 0; i < CH; i++) {
        int idx = base + i;
        if (idx < NN) {
            g_off[idx] = run;
            g_cur[idx] = 0;
            run += g_deg[idx];
        }
    }
    if (t == 1023) g_off[NN] = sh[1023];
}

__global__ void k_scatter(const int* __restrict__ ei) {
    int idx = blockIdx.x * blockDim.x + threadIdx.x;
    if (idx >= TE) return;
    int s, d;
    if (idx < NE) { s = ei[idx]; d = ei[NE + idx]; }
    else          { s = d = idx - NE; }
    int p = g_off[d] + atomicAdd(&g_cur[d], 1);
    g_csrc[p] = s;
}

// ---------------- helpers ---------------------------------------------------
__device__ __forceinline__ uint32_t s2u(const void* p) {
    return (uint32_t)__cvta_generic_to_shared(p);
}
__device__ __forceinline__ void cpa16(uint32_t dst, const void* src) {
    asm volatile("cp.async.cg.shared.global [%0], [%1], 16;"
                 :: "r"(dst), "l"(src));
}
__device__ __forceinline__ void cpa16p(uint32_t dst, const void* src, int sz) {
    asm volatile("cp.async.cg.shared.global [%0], [%1], 16, %2;"
                 :: "r"(dst), "l"(src), "r"(sz));
}
__device__ __forceinline__ float to_tf32(float x) {
    float r;
    asm("cvt.rna.tf32.f32 %0, %1;" : "=f"(r) : "f"(x));
    return r;
}

// ---------------- tf32 GEMM + fused attention epilogue ----------------------
// W stays fp32->tf32: shared quantization of W propagates coherently through
// pooling - never quantize it. C-store type: fp8 (layer 1) or bf16 (layer 2).
#define BS_LD 136
#define B_BYTES (2 * 32 * BS_LD * 4)
#define EXTRA_BYTES ((256 + 1024) * 4)

template <typename AT, bool FP8OUT>
__global__ __launch_bounds__(256, 2) void k_gemm_attn(const AT* __restrict__ A,
                                                      const float* __restrict__ B,
                                                      unsigned char* __restrict__ Cv,
                                                      const float* __restrict__ att_s,
                                                      const float* __restrict__ att_d,
                                                      int M) {
    constexpr bool A32 = (sizeof(AT) == 4);
    constexpr int AS_LDW = A32 ? 36 : 40;
    constexpr int A_BYTES = 2 * 128 * AS_LDW * (int)sizeof(AT);

    extern __shared__ char smc[];
    AT (*As)[128][AS_LDW] = reinterpret_cast<AT (*)[128][AS_LDW]>(smc);
    float (*Bs)[32][BS_LD] = reinterpret_cast<float (*)[32][BS_LD]>(smc + A_BYTES);
    float* satt = reinterpret_cast<float*>(smc + A_BYTES + B_BYTES);
    float* datt = satt + 128;
    float (*sps)[4] = reinterpret_cast<float (*)[4]>(datt + 128);
    float (*spd)[4] = reinterpret_cast<float (*)[4]>(datt + 128 + 512);

    const int tid = threadIdx.x;
    const int wid = tid >> 5, lane = tid & 31;
    const int warp_m = wid >> 2;
    const int warp_n = wid & 3;
    const int bm = blockIdx.x * 128;
    const int by = blockIdx.y;
    const int bn = by * 128;
    const int r = lane >> 2, c = lane & 3;

    if (tid < 128) {
        satt[tid] = att_s[by * 128 + tid];
        datt[tid] = att_d[by * 128 + tid];
    }

    float acc[4][4][4];
#pragma unroll
    for (int i = 0; i < 4; i++)
#pragma unroll
        for (int j = 0; j < 4; j++)
#pragma unroll
            for (int q = 0; q < 4; q++) acc[i][j][q] = 0.f;

    auto stage_load = [&](int st, int k0) {
        if constexpr (A32) {
#pragma unroll
            for (int i = 0; i < 4; i++) {
                int idx = tid + i * 256;
                int row = idx >> 3;
                int k4  = (idx & 7) << 2;
                cpa16p(s2u(&As[st][row][k4]), &A[(bm + row) * 256 + k0 + k4],
                       (bm + row < M) ? 16 : 0);
            }
        } else {
#pragma unroll
            for (int i = 0; i < 2; i++) {
                int idx = tid + i * 256;
                int row = idx >> 2;
                int k8  = (idx & 3) << 3;
                cpa16p(s2u(&As[st][row][k8]), &A[(bm + row) * 256 + k0 + k8],
                       (bm + row < M) ? 16 : 0);
            }
        }
#pragma unroll
        for (int i = 0; i < 4; i++) {
            int idx = tid + i * 256;
            int kk = idx >> 5;
            int n4 = (idx & 31) << 2;
            cpa16(s2u(&Bs[st][kk][n4]), &B[(k0 + kk) * 256 + bn + n4]);
        }
        asm volatile("cp.async.commit_group;");
    };

    auto afrag = [&](int cur, int m, int k) -> float {
        if constexpr (A32) return to_tf32(As[cur][m][k]);
        else               return __bfloat162float(As[cur][m][k]);
    };

    stage_load(0, 0);
    for (int t = 0; t < 8; t++) {
        const int cur = t & 1;
        if (t < 7) {
            stage_load(cur ^ 1, (t + 1) * 32);
            asm volatile("cp.async.wait_group 1;");
        } else {
            asm volatile("cp.async.wait_group 0;");
        }
        __syncthreads();
#pragma unroll
        for (int ks = 0; ks < 4; ks++) {
            const int kb = ks * 8;
            float a[4][4], b[4][2];
#pragma unroll
            for (int mt = 0; mt < 4; mt++) {
                int m0 = warp_m * 64 + mt * 16;
                a[mt][0] = afrag(cur, m0 + r, kb + c);
                a[mt][1] = afrag(cur, m0 + 8 + r, kb + c);
                a[mt][2] = afrag(cur, m0 + r, kb + 4 + c);
                a[mt][3] = afrag(cur, m0 + 8 + r, kb + 4 + c);
            }
#pragma unroll
            for (int nt = 0; nt < 4; nt++) {
                int n0 = warp_n * 32 + nt * 8;
                b[nt][0] = to_tf32(Bs[cur][kb + c][n0 + r]);
                b[nt][1] = to_tf32(Bs[cur][kb + 4 + c][n0 + r]);
            }
#pragma unroll
            for (int mt = 0; mt < 4; mt++)
#pragma unroll
                for (int nt = 0; nt < 4; nt++) {
                    asm volatile(
                        "mma.sync.aligned.m16n8k8.row.col.f32.tf32.tf32.f32 "
                        "{%0,%1,%2,%3}, {%4,%5,%6,%7}, {%8,%9}, {%0,%1,%2,%3};"
                        : "+f"(acc[mt][nt][0]), "+f"(acc[mt][nt][1]),
                          "+f"(acc[mt][nt][2]), "+f"(acc[mt][nt][3])
                        : "f"(a[mt][0]), "f"(a[mt][1]), "f"(a[mt][2]), "f"(a[mt][3]),
                          "f"(b[nt][0]), "f"(b[nt][1]));
                }
        }
        __syncthreads();
    }

    // ---- store C: fp8 (layer 1) or bf16 (layer 2) ----
#pragma unroll
    for (int mt = 0; mt < 4; mt++) {
        int row0 = bm + warp_m * 64 + mt * 16 + r;
#pragma unroll
        for (int nt = 0; nt < 4; nt++) {
            int col = bn + warp_n * 32 + nt * 8 + c * 2;
            if constexpr (FP8OUT) {
                if (row0 < M)
                    *(unsigned short*)&Cv[row0 * 256 + col] =
                        __nv_cvt_float2_to_fp8x2(
                            make_float2(acc[mt][nt][0], acc[mt][nt][1]),
                            __NV_SATFINITE, __NV_E4M3);
                if (row0 + 8 < M)
                    *(unsigned short*)&Cv[(row0 + 8) * 256 + col] =
                        __nv_cvt_float2_to_fp8x2(
                            make_float2(acc[mt][nt][2], acc[mt][nt][3]),
                            __NV_SATFINITE, __NV_E4M3);
            } else {
                __nv_bfloat16* Cb = (__nv_bfloat16*)Cv;
                if (row0 < M)
                    *(__nv_bfloat162*)&Cb[row0 * 256 + col] =
                        __floats2bfloat162_rn(acc[mt][nt][0], acc[mt][nt][1]);
                if (row0 + 8 < M)
                    *(__nv_bfloat162*)&Cb[(row0 + 8) * 256 + col] =
                        __floats2bfloat162_rn(acc[mt][nt][2], acc[mt][nt][3]);
            }
        }
    }

    // ---- fused attention epilogue (fp32 accs, pre-quantization) ----
    float ps[8], pd[8];
#pragma unroll
    for (int mt = 0; mt < 4; mt++) {
        float s_lo = 0.f, s_hi = 0.f, d_lo = 0.f, d_hi = 0.f;
#pragma unroll
        for (int nt = 0; nt < 4; nt++) {
            int cl = warp_n * 32 + nt * 8 + c * 2;
            float w0s = satt[cl], w1s = satt[cl + 1];
            float w0d = datt[cl], w1d = datt[cl + 1];
            s_lo += acc[mt][nt][0] * w0s + acc[mt][nt][1] * w1s;
            s_hi += acc[mt][nt][2] * w0s + acc[mt][nt][3] * w1s;
            d_lo += acc[mt][nt][0] * w0d + acc[mt][nt][1] * w1d;
            d_hi += acc[mt][nt][2] * w0d + acc[mt][nt][3] * w1d;
        }
        ps[mt * 2] = s_lo; ps[mt * 2 + 1] = s_hi;
        pd[mt * 2] = d_lo; pd[mt * 2 + 1] = d_hi;
    }
#pragma unroll
    for (int i = 0; i < 8; i++) {
        ps[i] += __shfl_xor_sync(0xffffffffu, ps[i], 1);
        ps[i] += __shfl_xor_sync(0xffffffffu, ps[i], 2);
        pd[i] += __shfl_xor_sync(0xffffffffu, pd[i], 1);
        pd[i] += __shfl_xor_sync(0xffffffffu, pd[i], 2);
    }
    if (c == 0) {
#pragma unroll
        for (int mt = 0; mt < 4; mt++) {
            int rl = warp_m * 64 + mt * 16 + r;
            sps[rl][warp_n]     = ps[mt * 2];
            spd[rl][warp_n]     = pd[mt * 2];
            sps[rl + 8][warp_n] = ps[mt * 2 + 1];
            spd[rl + 8][warp_n] = pd[mt * 2 + 1];
        }
    }
    __syncthreads();
    {
        int row = tid & 127;
        int hh  = tid >> 7;
        if (bm + row < M) {
            float vs = sps[row][hh * 2] + sps[row][hh * 2 + 1];
            float vd = spd[row][hh * 2] + spd[row][hh * 2 + 1];
            g_asrc[(bm + row) * 4 + by * 2 + hh] = vs;
            g_adst[(bm + row) * 4 + by * 2 + hh] = vd;
        }
    }
}

#define GEMM_SMEM_F32  (2 * 128 * 36 * 4 + B_BYTES + EXTRA_BYTES)
#define GEMM_SMEM_BF16 (2 * 128 * 40 * 2 + B_BYTES + EXTRA_BYTES)

// ---------------- message load+fma: fp8 or bf16 ------------------------------
template <bool FP8>
__device__ __forceinline__ void msg_fma(const unsigned char* p, float ex, float* a) {
    float2 f0, f1, f2, f3;
    if constexpr (FP8) {
        uint2 q = *(const uint2*)p;                       // 8 x e4m3
        __half2_raw r0 = __nv_cvt_fp8x2_to_halfraw2((__nv_fp8x2_storage_t)(q.x & 0xFFFFu), __NV_E4M3);
        __half2_raw r1 = __nv_cvt_fp8x2_to_halfraw2((__nv_fp8x2_storage_t)(q.x >> 16),     __NV_E4M3);
        __half2_raw r2 = __nv_cvt_fp8x2_to_halfraw2((__nv_fp8x2_storage_t)(q.y & 0xFFFFu), __NV_E4M3);
        __half2_raw r3 = __nv_cvt_fp8x2_to_halfraw2((__nv_fp8x2_storage_t)(q.y >> 16),     __NV_E4M3);
        f0 = __half22float2(*(__half2*)&r0);
        f1 = __half22float2(*(__half2*)&r1);
        f2 = __half22float2(*(__half2*)&r2);
        f3 = __half22float2(*(__half2*)&r3);
    } else {
        uint4 q = *(const uint4*)p;                       // 8 x bf16
        f0 = __bfloat1622float2(*(const __nv_bfloat162*)&q.x);
        f1 = __bfloat1622float2(*(const __nv_bfloat162*)&q.y);
        f2 = __bfloat1622float2(*(const __nv_bfloat162*)&q.z);
        f3 = __bfloat1622float2(*(const __nv_bfloat162*)&q.w);
    }
    a[0] = fmaf(f0.x, ex, a[0]); a[1] = fmaf(f0.y, ex, a[1]);
    a[2] = fmaf(f1.x, ex, a[2]); a[3] = fmaf(f1.y, ex, a[3]);
    a[4] = fmaf(f2.x, ex, a[4]); a[5] = fmaf(f2.y, ex, a[5]);
    a[6] = fmaf(f3.x, ex, a[6]); a[7] = fmaf(f3.y, ex, a[7]);
}

// ---------------- single-pass gather aggregate (round-11 form) ---------------
template <bool FP8>
__global__ __launch_bounds__(256) void k_agg(const unsigned char* __restrict__ h,
                                             const float* __restrict__ bias,
                                             __nv_bfloat16* __restrict__ feat) {
    constexpr int EB = FP8 ? 1 : 2;      // bytes per element
    const int warp = (blockIdx.x * blockDim.x + threadIdx.x) >> 5;
    const int lane = threadIdx.x & 31;
    if (warp >= NN) return;
    const int node = warp;
    const int beg = g_off[node], end = g_off[node + 1];
    const int h4 = lane >> 3;
    const float adh = g_adst[node * 4 + h4];
    const int loff = lane * 8 * EB;

    float dn = 0.f;
    float a[8] = {0.f, 0.f, 0.f, 0.f, 0.f, 0.f, 0.f, 0.f};

    int j = beg;
    for (; j + 3 < end; j += 4) {
        int s0 = g_csrc[j],     s1 = g_csrc[j + 1];
        int s2 = g_csrc[j + 2], s3 = g_csrc[j + 3];
        float e0 = g_asrc[s0 * 4 + h4] + adh;
        float e1 = g_asrc[s1 * 4 + h4] + adh;
        float e2 = g_asrc[s2 * 4 + h4] + adh;
        float e3 = g_asrc[s3 * 4 + h4] + adh;
        const unsigned char* p0 = h + (size_t)s0 * 256 * EB + loff;
        const unsigned char* p1 = h + (size_t)s1 * 256 * EB + loff;
        const unsigned char* p2 = h + (size_t)s2 * 256 * EB + loff;
        const unsigned char* p3 = h + (size_t)s3 * 256 * EB + loff;
        e0 = e0 > 0.f ? e0 : 0.2f * e0;  e1 = e1 > 0.f ? e1 : 0.2f * e1;
        e2 = e2 > 0.f ? e2 : 0.2f * e2;  e3 = e3 > 0.f ? e3 : 0.2f * e3;
        float x0 = __expf(e0), x1 = __expf(e1);
        float x2 = __expf(e2), x3 = __expf(e3);
        dn += (x0 + x1) + (x2 + x3);
        msg_fma<FP8>(p0, x0, a);
        msg_fma<FP8>(p1, x1, a);
        msg_fma<FP8>(p2, x2, a);
        msg_fma<FP8>(p3, x3, a);
    }
    for (; j < end; j++) {
        int s = g_csrc[j];
        float e = g_asrc[s * 4 + h4] + adh;
        e = e > 0.f ? e : 0.2f * e;
        float ex = __expf(e);
        dn += ex;
        msg_fma<FP8>(h + (size_t)s * 256 * EB + loff, ex, a);
    }

    const float inv = 1.f / (dn + 1e-16f);
    float4 b0 = *(const float4*)&bias[lane * 8];
    float4 b1 = *(const float4*)&bias[lane * 8 + 4];
    float o[8];
    o[0] = fmaf(a[0], inv, b0.x); o[1] = fmaf(a[1], inv, b0.y);
    o[2] = fmaf(a[2], inv, b0.z); o[3] = fmaf(a[3], inv, b0.w);
    o[4] = fmaf(a[4], inv, b1.x); o[5] = fmaf(a[5], inv, b1.y);
    o[6] = fmaf(a[6], inv, b1.z); o[7] = fmaf(a[7], inv, b1.w);
#pragma unroll
    for (int i = 0; i < 8; i++) o[i] = o[i] > 0.f ? o[i] : 0.f;
    uint4 qo;
    *(__nv_bfloat162*)&qo.x = __floats2bfloat162_rn(o[0], o[1]);
    *(__nv_bfloat162*)&qo.y = __floats2bfloat162_rn(o[2], o[3]);
    *(__nv_bfloat162*)&qo.z = __floats2bfloat162_rn(o[4], o[5]);
    *(__nv_bfloat162*)&qo.w = __floats2bfloat162_rn(o[6], o[7]);
    *(uint4*)&feat[node * 256 + lane * 8] = qo;
}

// ---------------- fused pool (sorted batch) + head --------------------------
__global__ __launch_bounds__(256) void k_poolhead(const int* __restrict__ batch,
                                                  const float* __restrict__ Wf,
                                                  const float* __restrict__ bf,
                                                  float* __restrict__ out,
                                                  int out_size) {
    const int g = blockIdx.x;
    const int t = threadIdx.x;
    __shared__ int s_bnd[2];
    __shared__ float sp[256];
    if (t < 2) {
        int key = g + t;
        int lo = 0, hi = NN;
        while (lo < hi) {
            int mid = (lo + hi) >> 1;
            if (batch[mid] < key) lo = mid + 1; else hi = mid;
        }
        s_bnd[t] = lo;
    }
    __syncthreads();
    const int lo = s_bnd[0], hi = s_bnd[1];
    float s0 = 0.f, s1 = 0.f, s2 = 0.f, s3 = 0.f;
    float s4 = 0.f, s5 = 0.f, s6 = 0.f, s7 = 0.f;
    int n = lo;
    for (; n + 7 < hi; n += 8) {
        s0 += __bfloat162float(g_feat[(n + 0) * 256 + t]);
        s1 += __bfloat162float(g_feat[(n + 1) * 256 + t]);
        s2 += __bfloat162float(g_feat[(n + 2) * 256 + t]);
        s3 += __bfloat162float(g_feat[(n + 3) * 256 + t]);
        s4 += __bfloat162float(g_feat[(n + 4) * 256 + t]);
        s5 += __bfloat162float(g_feat[(n + 5) * 256 + t]);
        s6 += __bfloat162float(g_feat[(n + 6) * 256 + t]);
        s7 += __bfloat162float(g_feat[(n + 7) * 256 + t]);
    }
    for (; n < hi; n++) s0 += __bfloat162float(g_feat[n * 256 + t]);
    float cnt = (float)(hi - lo);
    cnt = cnt < 1.f ? 1.f : cnt;
    float p = (((s0 + s1) + (s2 + s3)) + ((s4 + s5) + (s6 + s7))) / cnt;
    if (out_size >= NG * OD + NG * FDIM)
        out[NG * OD + g * 256 + t] = p;
    sp[t] = p;
    __syncthreads();
    if (t < OD) {
        float s = 0.f;
        for (int c = 0; c < 256; c++) s += sp[c] * Wf[c * OD + t];
        out[g * OD + t] = s + bf[t];
    }
}

// ---------------- launch ---------------------------------------------------
extern "C" void kernel_launch(void* const* d_in, const int* in_sizes, int n_in,
                              void* d_out, int out_size) {
    const float* x     = (const float*)d_in[0];
    const int*   ei    = (const int*)d_in[1];
    const int*   batch = (const int*)d_in[3];
    const float* W1  = (const float*)d_in[4];
    const float* as1 = (const float*)d_in[5];
    const float* ad1 = (const float*)d_in[6];
    const float* b1  = (const float*)d_in[7];
    const float* W2  = (const float*)d_in[8];
    const float* as2 = (const float*)d_in[9];
    const float* ad2 = (const float*)d_in[10];
    const float* b2  = (const float*)d_in[11];
    const float* Wf  = (const float*)d_in[12];
    const float* bf  = (const float*)d_in[13];
    float* out = (float*)d_out;

    unsigned char* p_h;
    __nv_bfloat16* p_feat;
    int* p_deg;
    cudaGetSymbolAddress((void**)&p_h, g_h);
    cudaGetSymbolAddress((void**)&p_feat, g_feat);
    cudaGetSymbolAddress((void**)&p_deg, g_deg);

    // lazily created once (first call = correctness run, outside graph capture)
    static cudaStream_t s_side = nullptr;
    static cudaEvent_t  ev_fork = nullptr, ev_join = nullptr;
    static bool s_attr_done = false;
    if (!s_side) {
        cudaStreamCreateWithFlags(&s_side, cudaStreamNonBlocking);
        cudaEventCreateWithFlags(&ev_fork, cudaEventDisableTiming);
        cudaEventCreateWithFlags(&ev_join, cudaEventDisableTiming);
    }
    if (!s_attr_done) {
        cudaFuncSetAttribute(k_gemm_attn<float, true>,
                             cudaFuncAttributeMaxDynamicSharedMemorySize,
                             GEMM_SMEM_F32);
        cudaFuncSetAttribute(k_gemm_attn<__nv_bfloat16, false>,
                             cudaFuncAttributeMaxDynamicSharedMemorySize,
                             GEMM_SMEM_BF16);
        s_attr_done = true;
    }

    const int GEMM_MB = (NN + 127) / 128;
    const int TE_BLK  = (TE + 255) / 256;
    const int AGG_BLK = (NN + 7) / 8;    // 8 warps/block

    // ---- fork: CSR build on side stream, overlapped with layer-1 GEMM ----
    cudaEventRecord(ev_fork, 0);
    cudaStreamWaitEvent(s_side, ev_fork, 0);
    cudaMemsetAsync(p_deg, 0, NN * sizeof(int), s_side);
    k_count<<<TE_BLK, 256, 0, s_side>>>(ei);
    k_scan<<<1, 1024, 0, s_side>>>();
    k_scatter<<<TE_BLK, 256, 0, s_side>>>(ei);
    cudaEventRecord(ev_join, s_side);

    // ---- layer 1: GEMM (fp8 message store) ----
    k_gemm_attn<float, true><<<dim3(GEMM_MB, 2), 256, GEMM_SMEM_F32>>>(
        x, W1, p_h, as1, ad1, NN);

    // ---- join: agg needs both CSR and GEMM-1 results ----
    cudaStreamWaitEvent(0, ev_join, 0);
    k_agg<true><<<AGG_BLK, 256>>>(p_h, b1, p_feat);

    // ---- layer 2: GEMM (bf16 message store) ----
    k_gemm_attn<__nv_bfloat16, false><<<dim3(GEMM_MB, 2), 256, GEMM_SMEM_BF16>>>(
        p_feat, W2, p_h, as2, ad2, NN);
    k_agg<false><<<AGG_BLK, 256>>>(p_h, b2, p_feat);

    // ---- fused pool + head ----
    k_poolhead<<<NG, 256>>>(batch, Wf, bf, out, out_size);
}